// round 6
// baseline (speedup 1.0000x reference)
#include <cuda_runtime.h>
#include <cstdint>
#include <cstddef>

// DecorrelationGradient: out = 0.5 * (X^T X)/N - 0.5   (KAPPA = 0.5 exact algebraic collapse)
// X: [N=16384, 768] fp32 row-major.  out: [768, 768] fp32.
//
// Plan: symmetric-tiled TF32 SYRK (mma.sync.m16n8k8) with split-K=14 into a
// __device__ partial buffer (deterministic, no atomics), then a reduce kernel
// applying the affine epilogue.

#define D        768
#define BT       128          // output tile (BT x BT)
#define NT       6            // D / BT
#define NTILES   21           // NT*(NT+1)/2 upper-triangular tiles
#define KC       16           // K rows per pipeline stage
#define NSPLIT   14           // split-K factor: 21*14 = 294 CTAs (one wave @ occ 2)
#define PAD      136          // 128 + 8 floats padded row stride (bank-conflict-free frags)

__device__ float g_part[(size_t)NSPLIT * D * D];   // 33 MB static scratch (allowed)

__device__ __forceinline__ uint32_t f2tf32(float f) {
    uint32_t u;
    asm("cvt.rna.tf32.f32 %0, %1;" : "=r"(u) : "f"(f));
    return u;
}

__device__ __forceinline__ uint32_t saddr(const void* p) {
    return (uint32_t)__cvta_generic_to_shared(p);
}

__device__ __forceinline__ void cp16(uint32_t s, const float* g) {
    asm volatile("cp.async.cg.shared.global [%0], [%1], 16;" :: "r"(s), "l"(g));
}

__device__ __forceinline__ void load_slabs(float (*sA)[PAD], float (*sB)[PAD],
                                           const float* gA, const float* gB, int tid) {
    // one KC x 128 slab = 512 float4; 256 threads -> 2 float4 each (per slab)
#pragma unroll
    for (int i = 0; i < 2; i++) {
        int idx = tid + i * 256;
        int row = idx >> 5;             // 0..15
        int c4  = (idx & 31) << 2;      // 0,4,...,124
        cp16(saddr(&sA[row][c4]), gA + (size_t)row * D + c4);
        cp16(saddr(&sB[row][c4]), gB + (size_t)row * D + c4);
    }
    asm volatile("cp.async.commit_group;" ::: "memory");
}

__global__ __launch_bounds__(256, 2)
void gram_tf32_kernel(const float* __restrict__ x, int kc_total) {
    int bx    = blockIdx.x;
    int tile  = bx % NTILES;
    int split = bx / NTILES;

    // tile -> (I, J) with I <= J
    int I = 0, t = tile;
    while (t >= NT - I) { t -= NT - I; I++; }
    int J = I + t;

    int kc0 = (int)((long long)split * kc_total / NSPLIT);
    int kc1 = (int)((long long)(split + 1) * kc_total / NSPLIT);
    int nch = kc1 - kc0;

    __shared__ float sA[2][KC][PAD];
    __shared__ float sB[2][KC][PAD];

    int tid  = threadIdx.x;
    int lane = tid & 31;
    int warp = tid >> 5;
    int wm   = warp & 1;     // 2 warps along M (64 rows each)
    int wn   = warp >> 1;    // 4 warps along N (32 cols each)

    const int colA = I * BT;
    const int colB = J * BT;

    float c[4][4][4];
#pragma unroll
    for (int mi = 0; mi < 4; mi++)
#pragma unroll
        for (int ni = 0; ni < 4; ni++)
#pragma unroll
            for (int r = 0; r < 4; r++) c[mi][ni][r] = 0.0f;

    if (nch > 0) {
        load_slabs(sA[0], sB[0],
                   x + (size_t)kc0 * KC * D + colA,
                   x + (size_t)kc0 * KC * D + colB, tid);

        for (int ch = 0; ch < nch; ch++) {
            int buf = ch & 1;
            asm volatile("cp.async.wait_group 0;" ::: "memory");
            __syncthreads();
            if (ch + 1 < nch) {
                size_t kb = (size_t)(kc0 + ch + 1) * KC * D;
                load_slabs(sA[buf ^ 1], sB[buf ^ 1], x + kb + colA, x + kb + colB, tid);
            }

            // compute on buf: KC=16 -> two k8 steps
#pragma unroll
            for (int kk = 0; kk < KC; kk += 8) {
                int krow  = kk + (lane & 3);
                int mbase = wm * 64 + (lane >> 2);
                int nbase = wn * 32 + (lane >> 2);

                uint32_t a[4][4];
#pragma unroll
                for (int mi = 0; mi < 4; mi++) {
                    int m = mbase + mi * 16;
                    a[mi][0] = f2tf32(sA[buf][krow][m]);
                    a[mi][1] = f2tf32(sA[buf][krow][m + 8]);
                    a[mi][2] = f2tf32(sA[buf][krow + 4][m]);
                    a[mi][3] = f2tf32(sA[buf][krow + 4][m + 8]);
                }
                uint32_t bf[4][2];
#pragma unroll
                for (int ni = 0; ni < 4; ni++) {
                    int n = nbase + ni * 8;
                    bf[ni][0] = f2tf32(sB[buf][krow][n]);
                    bf[ni][1] = f2tf32(sB[buf][krow + 4][n]);
                }
#pragma unroll
                for (int mi = 0; mi < 4; mi++)
#pragma unroll
                    for (int ni = 0; ni < 4; ni++) {
                        asm volatile(
                            "mma.sync.aligned.m16n8k8.row.col.f32.tf32.tf32.f32 "
                            "{%0,%1,%2,%3}, {%4,%5,%6,%7}, {%8,%9}, {%0,%1,%2,%3};"
                            : "+f"(c[mi][ni][0]), "+f"(c[mi][ni][1]),
                              "+f"(c[mi][ni][2]), "+f"(c[mi][ni][3])
                            : "r"(a[mi][0]), "r"(a[mi][1]), "r"(a[mi][2]), "r"(a[mi][3]),
                              "r"(bf[ni][0]), "r"(bf[ni][1]));
                    }
            }
        }
    }

    // epilogue: write raw partial sums for this split (direct + mirrored block)
    float* part = g_part + (size_t)split * D * D;
    int mw = I * BT + wm * 64 + (lane >> 2);
    int nw = J * BT + wn * 32 + 2 * (lane & 3);

#pragma unroll
    for (int mi = 0; mi < 4; mi++) {
        int m = mw + mi * 16;
#pragma unroll
        for (int ni = 0; ni < 4; ni++) {
            int n = nw + ni * 8;
            float2 v0 = make_float2(c[mi][ni][0], c[mi][ni][1]);
            float2 v1 = make_float2(c[mi][ni][2], c[mi][ni][3]);
            *(float2*)&part[(size_t)m * D + n]       = v0;
            *(float2*)&part[(size_t)(m + 8) * D + n] = v1;
        }
    }
    if (I != J) {
#pragma unroll
        for (int mi = 0; mi < 4; mi++) {
            int m = mw + mi * 16;
#pragma unroll
            for (int ni = 0; ni < 4; ni++) {
                int n = nw + ni * 8;
                part[(size_t)n * D + m]           = c[mi][ni][0];
                part[(size_t)(n + 1) * D + m]     = c[mi][ni][1];
                part[(size_t)n * D + m + 8]       = c[mi][ni][2];
                part[(size_t)(n + 1) * D + m + 8] = c[mi][ni][3];
            }
        }
    }
}

__global__ void reduce_kernel(float4* __restrict__ out4, float invN) {
    int idx = blockIdx.x * blockDim.x + threadIdx.x;
    const int n4 = D * D / 4;
    if (idx >= n4) return;
    const float4* p = (const float4*)g_part;
    float ax = 0.f, ay = 0.f, az = 0.f, aw = 0.f;
#pragma unroll
    for (int s = 0; s < NSPLIT; s++) {
        float4 v = p[(size_t)s * n4 + idx];
        ax += v.x; ay += v.y; az += v.z; aw += v.w;
    }
    float h = 0.5f * invN;
    out4[idx] = make_float4(fmaf(h, ax, -0.5f), fmaf(h, ay, -0.5f),
                            fmaf(h, az, -0.5f), fmaf(h, aw, -0.5f));
}

extern "C" void kernel_launch(void* const* d_in, const int* in_sizes, int n_in,
                              void* d_out, int out_size) {
    const float* x = (const float*)d_in[0];
    float* out = (float*)d_out;
    int N = in_sizes[0] / D;        // 16384
    int kc_total = N / KC;          // 1024

    gram_tf32_kernel<<<NTILES * NSPLIT, 256>>>(x, kc_total);

    float invN = 1.0f / (float)N;
    int n4 = D * D / 4;
    reduce_kernel<<<(n4 + 255) / 256, 256>>>((float4*)out, invN);
}

// round 9
// speedup vs baseline: 1.3925x; 1.3925x over previous
#include <cuda_runtime.h>
#include <cuda_bf16.h>
#include <cstdint>
#include <cstddef>

// DecorrelationGradient: out = 0.5 * (X^T X)/N - 0.5   (KAPPA = 0.5 algebraic collapse)
// X: [16384, 768] fp32.  out: [768, 768] fp32.
//
// Pipeline: (1) convert X -> bf16 transposed Xt[768][16384] (k-contiguous),
// (2) symmetric-tiled bf16 SYRK via mma.sync.m16n8k16 + ldmatrix, split-K=14
// deterministic partials, (3) shuffle-parallel reduce + affine epilogue.
// (tcgen05 is unavailable: harness PTX targets compute_103 without the 'a' feature set.)

#define D        768
#define NROW     16384
#define BT       128
#define NT       6
#define NTILES   21
#define NSPLIT   14
#define KCH      64                     // k elements per pipeline chunk
#define KSTRIDE  144                    // 128B data + 16B pad per smem row
#define TILE_B   (BT * KSTRIDE)         // 18432
#define STAGE_B  (2 * TILE_B)           // 36864
#define NSTAGE   3
#define DYN_SMEM (NSTAGE * STAGE_B)     // 110592

__device__ float g_part[(size_t)NSPLIT * D * D];                 // 33 MB
__device__ __align__(16) __nv_bfloat16 g_xt[(size_t)D * NROW];   // 24 MB

__device__ __forceinline__ uint32_t saddr(const void* p) {
    return (uint32_t)__cvta_generic_to_shared(p);
}
__device__ __forceinline__ void cp16(uint32_t s, const void* g) {
    asm volatile("cp.async.cg.shared.global [%0], [%1], 16;" :: "r"(s), "l"(g));
}

#define LDMX4(R, A) \
    asm volatile("ldmatrix.sync.aligned.m8n8.x4.shared.b16 {%0,%1,%2,%3}, [%4];" \
        : "=r"((R)[0]), "=r"((R)[1]), "=r"((R)[2]), "=r"((R)[3]) : "r"(A))

#define MMA16816(C, A, B0, B1) \
    asm volatile("mma.sync.aligned.m16n8k16.row.col.f32.bf16.bf16.f32 " \
        "{%0,%1,%2,%3}, {%4,%5,%6,%7}, {%8,%9}, {%0,%1,%2,%3};" \
        : "+f"((C)[0]), "+f"((C)[1]), "+f"((C)[2]), "+f"((C)[3]) \
        : "r"((A)[0]), "r"((A)[1]), "r"((A)[2]), "r"((A)[3]), "r"(B0), "r"(B1))

// ---------------------------------------------------------------------------
// 1) Transpose + convert: Xt[d][n] = bf16(X[n][d])
// ---------------------------------------------------------------------------
__global__ void __launch_bounds__(256)
xt_kernel(const float* __restrict__ x) {
    __shared__ float s[32][33];
    int tx = threadIdx.x, ty = threadIdx.y;          // 16 x 16
    int d0 = blockIdx.x * 32, n0 = blockIdx.y * 32;

#pragma unroll
    for (int i = 0; i < 32; i += 16) {
        float2 v = *(const float2*)&x[(size_t)(n0 + ty + i) * D + d0 + 2 * tx];
        s[ty + i][2 * tx]     = v.x;
        s[ty + i][2 * tx + 1] = v.y;
    }
    __syncthreads();
#pragma unroll
    for (int i = 0; i < 32; i += 16) {
        int dr = ty + i;
        __nv_bfloat162 h;
        h.x = __float2bfloat16_rn(s[2 * tx][dr]);
        h.y = __float2bfloat16_rn(s[2 * tx + 1][dr]);
        *(__nv_bfloat162*)&g_xt[(size_t)(d0 + dr) * NROW + n0 + 2 * tx] = h;
    }
}

// ---------------------------------------------------------------------------
// 2) bf16 SYRK: 128x128 tiles, 8 warps (2m x 4n), 64x32 per warp
// ---------------------------------------------------------------------------
__device__ __forceinline__ void load_chunk(uint32_t sA, const __nv_bfloat16* gA,
                                           const __nv_bfloat16* gB, int k0,
                                           bool diag, int tid) {
#pragma unroll
    for (int i = 0; i < 4; i++) {
        int idx = tid + i * 256;        // 0..1023
        int m   = idx >> 3;             // 0..127
        int ch  = idx & 7;              // 16B chunk in row
        uint32_t dst = (uint32_t)m * KSTRIDE + (uint32_t)ch * 16;
        cp16(sA + dst, gA + (size_t)m * NROW + k0 + ch * 8);
        if (!diag)
            cp16(sA + TILE_B + dst, gB + (size_t)m * NROW + k0 + ch * 8);
    }
    asm volatile("cp.async.commit_group;" ::: "memory");
}

extern __shared__ char dyn_smem[];

__global__ void __launch_bounds__(256, 2)
gram_bf16(int nchunks_total) {
    int bx = blockIdx.x;
    int tile = bx % NTILES, split = bx / NTILES;
    int I = 0, t = tile;
    while (t >= NT - I) { t -= NT - I; I++; }
    int J = I + t;
    bool diag = (I == J);

    int c0 = split * nchunks_total / NSPLIT;
    int c1 = (split + 1) * nchunks_total / NSPLIT;
    int nch = c1 - c0;

    int tid = threadIdx.x, lane = tid & 31, warp = tid >> 5;
    int wm = warp & 1, wn = warp >> 1;
    int r = lane & 7, sel = lane >> 3;

    const __nv_bfloat16* gA = g_xt + (size_t)(I * BT) * NROW;
    const __nv_bfloat16* gB = g_xt + (size_t)(J * BT) * NROW;
    uint32_t sbase = saddr(dyn_smem);

    // per-lane ldmatrix address offsets (within a tile buffer)
    uint32_t aoff = (uint32_t)(wm * 64 + r + ((sel & 1) << 3)) * KSTRIDE +
                    ((uint32_t)(sel >> 1) << 4);
    uint32_t boff = (uint32_t)(wn * 32 + r + ((sel >> 1) << 3)) * KSTRIDE +
                    ((uint32_t)(sel & 1) << 4);

    float c[4][4][4];
#pragma unroll
    for (int mi = 0; mi < 4; mi++)
#pragma unroll
        for (int ni = 0; ni < 4; ni++)
#pragma unroll
            for (int q = 0; q < 4; q++) c[mi][ni][q] = 0.0f;

    // prologue: 3 stages
#pragma unroll
    for (int p = 0; p < NSTAGE; p++)
        load_chunk(sbase + p * STAGE_B, gA, gB, (c0 + p) * KCH, diag, tid);

    for (int ch = 0; ch < nch; ch++) {
        int left = nch - 1 - ch;
        if (left >= 2)      asm volatile("cp.async.wait_group 2;" ::: "memory");
        else if (left == 1) asm volatile("cp.async.wait_group 1;" ::: "memory");
        else                asm volatile("cp.async.wait_group 0;" ::: "memory");
        __syncthreads();

        uint32_t sA = sbase + (ch % NSTAGE) * STAGE_B;
        uint32_t sB = diag ? sA : sA + TILE_B;

#pragma unroll
        for (int step = 0; step < KCH / 16; step++) {
            uint32_t kb = step * 32;
            uint32_t a[4][4];
#pragma unroll
            for (int mi = 0; mi < 4; mi++)
                LDMX4(a[mi], sA + aoff + mi * (16 * KSTRIDE) + kb);
            uint32_t b[2][4];
#pragma unroll
            for (int p = 0; p < 2; p++)
                LDMX4(b[p], sB + boff + p * (16 * KSTRIDE) + kb);
#pragma unroll
            for (int mi = 0; mi < 4; mi++)
#pragma unroll
                for (int ni = 0; ni < 4; ni++) {
                    uint32_t* bp = b[ni >> 1];
                    if (ni & 1) MMA16816(c[mi][ni], a[mi], bp[2], bp[3]);
                    else        MMA16816(c[mi][ni], a[mi], bp[0], bp[1]);
                }
        }
        __syncthreads();

        int nxt = ch + NSTAGE;
        if (nxt < nch)
            load_chunk(sbase + (nxt % NSTAGE) * STAGE_B, gA, gB,
                       (c0 + nxt) * KCH, diag, tid);
    }

    // epilogue: raw partial sums (direct + mirrored block) — validated in R5
    float* part = g_part + (size_t)split * D * D;
    int mw = I * BT + wm * 64 + (lane >> 2);
    int nw = J * BT + wn * 32 + 2 * (lane & 3);

#pragma unroll
    for (int mi = 0; mi < 4; mi++) {
        int m = mw + mi * 16;
#pragma unroll
        for (int ni = 0; ni < 4; ni++) {
            int n = nw + ni * 8;
            *(float2*)&part[(size_t)m * D + n] =
                make_float2(c[mi][ni][0], c[mi][ni][1]);
            *(float2*)&part[(size_t)(m + 8) * D + n] =
                make_float2(c[mi][ni][2], c[mi][ni][3]);
        }
    }
    if (!diag) {
#pragma unroll
        for (int mi = 0; mi < 4; mi++) {
            int m = mw + mi * 16;
#pragma unroll
            for (int ni = 0; ni < 4; ni++) {
                int n = nw + ni * 8;
                part[(size_t)n * D + m]           = c[mi][ni][0];
                part[(size_t)(n + 1) * D + m]     = c[mi][ni][1];
                part[(size_t)n * D + m + 8]       = c[mi][ni][2];
                part[(size_t)(n + 1) * D + m + 8] = c[mi][ni][3];
            }
        }
    }
}

// ---------------------------------------------------------------------------
// 3) Reduce: 2 threads per output float4 (7 splits each) + shfl combine
// ---------------------------------------------------------------------------
__global__ void __launch_bounds__(256)
reduce_kernel(float4* __restrict__ out4, float invN) {
    const int n4 = D * D / 4;
    int t = blockIdx.x * blockDim.x + threadIdx.x;   // 0 .. 2*n4-1
    int e = t >> 1, h = t & 1;
    const float4* p = (const float4*)g_part;

    float ax = 0.f, ay = 0.f, az = 0.f, aw = 0.f;
#pragma unroll
    for (int s = 0; s < 7; s++) {
        float4 v = p[(size_t)(h * 7 + s) * n4 + e];
        ax += v.x; ay += v.y; az += v.z; aw += v.w;
    }
    ax += __shfl_xor_sync(0xFFFFFFFFu, ax, 1);
    ay += __shfl_xor_sync(0xFFFFFFFFu, ay, 1);
    az += __shfl_xor_sync(0xFFFFFFFFu, az, 1);
    aw += __shfl_xor_sync(0xFFFFFFFFu, aw, 1);

    if (h == 0) {
        float hh = 0.5f * invN;
        out4[e] = make_float4(fmaf(hh, ax, -0.5f), fmaf(hh, ay, -0.5f),
                              fmaf(hh, az, -0.5f), fmaf(hh, aw, -0.5f));
    }
}

extern "C" void kernel_launch(void* const* d_in, const int* in_sizes, int n_in,
                              void* d_out, int out_size) {
    const float* x = (const float*)d_in[0];
    float* out = (float*)d_out;
    int N = in_sizes[0] / D;            // 16384
    int nchunks = N / KCH;              // 256

    xt_kernel<<<dim3(D / 32, N / 32), dim3(16, 16)>>>(x);

    cudaFuncSetAttribute(gram_bf16, cudaFuncAttributeMaxDynamicSharedMemorySize,
                         DYN_SMEM);
    gram_bf16<<<NTILES * NSPLIT, 256, DYN_SMEM>>>(nchunks);

    float invN = 1.0f / (float)N;
    int n4 = D * D / 4;
    reduce_kernel<<<(2 * n4) / 256, 256>>>((float4*)out, invN);
}

// round 10
// speedup vs baseline: 1.5529x; 1.1152x over previous
#include <cuda_runtime.h>
#include <cuda_bf16.h>
#include <cstdint>
#include <cstddef>

// DecorrelationGradient: out = 0.5 * (X^T X)/N - 0.5   (KAPPA = 0.5 algebraic collapse)
// X: [16384, 768] fp32.  out: [768, 768] fp32.
//
// (1) streaming fp32->bf16 convert (NO transpose; gram uses ldmatrix.trans),
// (2) symmetric-tiled bf16 SYRK via mma.sync.m16n8k16, k-row-major smem tiles,
//     single-sync 3-stage cp.async pipeline, split-K=14 deterministic partials,
// (3) shuffle-parallel reduce + affine epilogue.

#define D        768
#define NROW     16384
#define BT       128
#define NT       6
#define NTILES   21
#define NSPLIT   14
#define KCH      64                     // k samples per pipeline chunk
#define KSB      272                    // smem row stride: 128 m * 2B + 16B pad
#define TILE_B   (KCH * KSB)            // 17408
#define STAGE_B  (2 * TILE_B)           // 34816
#define NSTAGE   3
#define DYN_SMEM (NSTAGE * STAGE_B)     // 104448

__device__ float g_part[(size_t)NSPLIT * D * D];                 // 33 MB
__device__ __align__(16) __nv_bfloat16 g_xb[(size_t)NROW * D];   // 24 MB, same layout as X

__device__ __forceinline__ uint32_t saddr(const void* p) {
    return (uint32_t)__cvta_generic_to_shared(p);
}
__device__ __forceinline__ void cp16(uint32_t s, const void* g) {
    asm volatile("cp.async.cg.shared.global [%0], [%1], 16;" :: "r"(s), "l"(g));
}

#define LDMX4T(R, A) \
    asm volatile("ldmatrix.sync.aligned.m8n8.x4.trans.shared.b16 {%0,%1,%2,%3}, [%4];" \
        : "=r"((R)[0]), "=r"((R)[1]), "=r"((R)[2]), "=r"((R)[3]) : "r"(A))

#define MMA16816(C, A, B0, B1) \
    asm volatile("mma.sync.aligned.m16n8k16.row.col.f32.bf16.bf16.f32 " \
        "{%0,%1,%2,%3}, {%4,%5,%6,%7}, {%8,%9}, {%0,%1,%2,%3};" \
        : "+f"((C)[0]), "+f"((C)[1]), "+f"((C)[2]), "+f"((C)[3]) \
        : "r"((A)[0]), "r"((A)[1]), "r"((A)[2]), "r"((A)[3]), "r"(B0), "r"(B1))

// ---------------------------------------------------------------------------
// 1) Streaming convert: g_xb[i] = bf16(x[i]), fully coalesced
// ---------------------------------------------------------------------------
__global__ void __launch_bounds__(256)
cvt_kernel(const float* __restrict__ x) {
    size_t i = ((size_t)blockIdx.x * 256 + threadIdx.x) * 8;
    float4 v0 = *(const float4*)(x + i);
    float4 v1 = *(const float4*)(x + i + 4);
    union { __nv_bfloat162 h2[4]; uint4 u; } p;
    p.h2[0] = __floats2bfloat162_rn(v0.x, v0.y);
    p.h2[1] = __floats2bfloat162_rn(v0.z, v0.w);
    p.h2[2] = __floats2bfloat162_rn(v1.x, v1.y);
    p.h2[3] = __floats2bfloat162_rn(v1.z, v1.w);
    *(uint4*)(g_xb + i) = p.u;
}

// ---------------------------------------------------------------------------
// 2) bf16 SYRK: 128x128 tiles, 8 warps (2m x 4n), 64x32 per warp.
//    smem tile layout: [k][m], 64 k-rows of 128 bf16 (256B data + 16B pad).
// ---------------------------------------------------------------------------
__device__ __forceinline__ void load_chunk(uint32_t sA, int k0,
                                           int colA, int colB,
                                           bool diag, int tid) {
#pragma unroll
    for (int i = 0; i < 4; i++) {
        int idx = tid + i * 256;        // 0..1023
        int k   = idx >> 4;             // 0..63
        int ch  = idx & 15;             // 16B chunk in the 256B row
        uint32_t dst = (uint32_t)k * KSB + (uint32_t)ch * 16;
        const __nv_bfloat16* g = g_xb + (size_t)(k0 + k) * D + ch * 8;
        cp16(sA + dst, g + colA);
        if (!diag) cp16(sA + TILE_B + dst, g + colB);
    }
    asm volatile("cp.async.commit_group;" ::: "memory");
}

extern __shared__ char dyn_smem[];

__global__ void __launch_bounds__(256, 2)
gram_bf16(int nchunks_total) {
    int bx = blockIdx.x;
    int tile = bx % NTILES, split = bx / NTILES;
    int I = 0, t = tile;
    while (t >= NT - I) { t -= NT - I; I++; }
    int J = I + t;
    bool diag = (I == J);
    int colA = I * BT, colB = J * BT;

    int c0 = split * nchunks_total / NSPLIT;
    int c1 = (split + 1) * nchunks_total / NSPLIT;
    int nch = c1 - c0;

    int tid = threadIdx.x, lane = tid & 31, warp = tid >> 5;
    int wm = warp & 1, wn = warp >> 1;
    int r = lane & 7, sel = lane >> 3;
    uint32_t sbase = saddr(dyn_smem);

    // ldmatrix.x4.trans per-lane offsets (within a tile buffer):
    // A (16m x 16k): mat0..3 = (m0-7,k0-7),(m8-15,k0-7),(m0-7,k8-15),(m8-15,k8-15)
    //   lane addr = [krow = (sel>>1)*8 + r][mcol = mbase + (sel&1)*8]
    uint32_t aoff = (uint32_t)((sel >> 1) * 8 + r) * KSB +
                    (uint32_t)(wm * 64 + (sel & 1) * 8) * 2;
    // B (16n x 16k): mat0..3 = (k0-7,n0-7),(k8-15,n0-7),(k0-7,n8-15),(k8-15,n8-15)
    //   lane addr = [krow = (sel&1)*8 + r][ncol = nbase + (sel>>1)*8]
    uint32_t boff = (uint32_t)((sel & 1) * 8 + r) * KSB +
                    (uint32_t)(wn * 32 + (sel >> 1) * 8) * 2;

    float c[4][4][4];
#pragma unroll
    for (int mi = 0; mi < 4; mi++)
#pragma unroll
        for (int ni = 0; ni < 4; ni++)
#pragma unroll
            for (int q = 0; q < 4; q++) c[mi][ni][q] = 0.0f;

    // prologue: 2 chunks in flight
    load_chunk(sbase,           (c0 + 0) * KCH, colA, colB, diag, tid);
    load_chunk(sbase + STAGE_B, (c0 + 1) * KCH, colA, colB, diag, tid);

    for (int ch = 0; ch < nch; ch++) {
        if (ch < nch - 1) asm volatile("cp.async.wait_group 1;" ::: "memory");
        else              asm volatile("cp.async.wait_group 0;" ::: "memory");
        __syncthreads();
        // prefetch 2 ahead into slot (ch+2)%3 — its prior occupant (chunk ch-1)
        // was consumed by all warps before this barrier.
        int nxt = ch + 2;
        if (nxt < nch)
            load_chunk(sbase + (nxt % NSTAGE) * STAGE_B, (c0 + nxt) * KCH,
                       colA, colB, diag, tid);

        uint32_t sA = sbase + (ch % NSTAGE) * STAGE_B;
        uint32_t sB = diag ? sA : sA + TILE_B;

#pragma unroll
        for (int step = 0; step < KCH / 16; step++) {
            uint32_t kb = (uint32_t)step * (16 * KSB);
            uint32_t a[4][4];
#pragma unroll
            for (int mi = 0; mi < 4; mi++)
                LDMX4T(a[mi], sA + kb + aoff + mi * 32);        // +16 m = +32B
            uint32_t b[2][4];
#pragma unroll
            for (int p = 0; p < 2; p++)
                LDMX4T(b[p], sB + kb + boff + p * 32);          // +16 n = +32B
#pragma unroll
            for (int mi = 0; mi < 4; mi++)
#pragma unroll
                for (int ni = 0; ni < 4; ni++) {
                    uint32_t* bp = b[ni >> 1];
                    if (ni & 1) MMA16816(c[mi][ni], a[mi], bp[2], bp[3]);
                    else        MMA16816(c[mi][ni], a[mi], bp[0], bp[1]);
                }
        }
    }

    // epilogue: raw partial sums (direct + mirrored block)
    float* part = g_part + (size_t)split * D * D;
    int mw = I * BT + wm * 64 + (lane >> 2);
    int nw = J * BT + wn * 32 + 2 * (lane & 3);

#pragma unroll
    for (int mi = 0; mi < 4; mi++) {
        int m = mw + mi * 16;
#pragma unroll
        for (int ni = 0; ni < 4; ni++) {
            int n = nw + ni * 8;
            *(float2*)&part[(size_t)m * D + n] =
                make_float2(c[mi][ni][0], c[mi][ni][1]);
            *(float2*)&part[(size_t)(m + 8) * D + n] =
                make_float2(c[mi][ni][2], c[mi][ni][3]);
        }
    }
    if (!diag) {
#pragma unroll
        for (int mi = 0; mi < 4; mi++) {
            int m = mw + mi * 16;
#pragma unroll
            for (int ni = 0; ni < 4; ni++) {
                int n = nw + ni * 8;
                part[(size_t)n * D + m]           = c[mi][ni][0];
                part[(size_t)(n + 1) * D + m]     = c[mi][ni][1];
                part[(size_t)n * D + m + 8]       = c[mi][ni][2];
                part[(size_t)(n + 1) * D + m + 8] = c[mi][ni][3];
            }
        }
    }
}

// ---------------------------------------------------------------------------
// 3) Reduce: 2 threads per output float4 (7 splits each) + shfl combine
// ---------------------------------------------------------------------------
__global__ void __launch_bounds__(256)
reduce_kernel(float4* __restrict__ out4, float invN) {
    const int n4 = D * D / 4;
    int t = blockIdx.x * blockDim.x + threadIdx.x;   // 0 .. 2*n4-1
    int e = t >> 1, h = t & 1;
    const float4* p = (const float4*)g_part;

    float ax = 0.f, ay = 0.f, az = 0.f, aw = 0.f;
#pragma unroll
    for (int s = 0; s < 7; s++) {
        float4 v = p[(size_t)(h * 7 + s) * n4 + e];
        ax += v.x; ay += v.y; az += v.z; aw += v.w;
    }
    ax += __shfl_xor_sync(0xFFFFFFFFu, ax, 1);
    ay += __shfl_xor_sync(0xFFFFFFFFu, ay, 1);
    az += __shfl_xor_sync(0xFFFFFFFFu, az, 1);
    aw += __shfl_xor_sync(0xFFFFFFFFu, aw, 1);

    if (h == 0) {
        float hh = 0.5f * invN;
        out4[e] = make_float4(fmaf(hh, ax, -0.5f), fmaf(hh, ay, -0.5f),
                              fmaf(hh, az, -0.5f), fmaf(hh, aw, -0.5f));
    }
}

extern "C" void kernel_launch(void* const* d_in, const int* in_sizes, int n_in,
                              void* d_out, int out_size) {
    const float* x = (const float*)d_in[0];
    float* out = (float*)d_out;
    int N = in_sizes[0] / D;            // 16384
    int nchunks = N / KCH;              // 256

    int nelem = N * D;                  // 12,582,912
    cvt_kernel<<<nelem / (256 * 8), 256>>>(x);

    cudaFuncSetAttribute(gram_bf16, cudaFuncAttributeMaxDynamicSharedMemorySize,
                         DYN_SMEM);
    gram_bf16<<<NTILES * NSPLIT, 256, DYN_SMEM>>>(nchunks);

    float invN = 1.0f / (float)N;
    int n4 = D * D / 4;
    reduce_kernel<<<(2 * n4) / 256, 256>>>((float4*)out, invN);
}

// round 11
// speedup vs baseline: 1.5780x; 1.0162x over previous
#include <cuda_runtime.h>
#include <cuda_bf16.h>
#include <cstdint>
#include <cstddef>

// DecorrelationGradient: out = 0.5 * (X^T X)/N - 0.5   (KAPPA = 0.5 algebraic collapse)
// X: [16384, 768] fp32.  out: [768, 768] fp32.
//
// (1) init out = -0.5, (2) streaming fp32->bf16 convert (no transpose),
// (3) symmetric-tiled bf16 SYRK via mma.sync.m16n8k16 + ldmatrix.trans,
//     split-K=14, epilogue accumulates scaled fragments straight into out
//     via red.global.add (no partials buffer, no reduce kernel).

#define D        768
#define NROW     16384
#define BT       128
#define NT       6
#define NTILES   21
#define NSPLIT   14
#define KCH      64                     // k samples per pipeline chunk
#define KSB      272                    // smem row stride: 128 m * 2B + 16B pad
#define TILE_B   (KCH * KSB)            // 17408
#define STAGE_B  (2 * TILE_B)           // 34816
#define NSTAGE   3
#define DYN_SMEM (NSTAGE * STAGE_B)     // 104448

__device__ __align__(16) __nv_bfloat16 g_xb[(size_t)NROW * D];   // 24 MB bf16 copy of X

__device__ __forceinline__ uint32_t saddr(const void* p) {
    return (uint32_t)__cvta_generic_to_shared(p);
}
__device__ __forceinline__ void cp16(uint32_t s, const void* g) {
    asm volatile("cp.async.cg.shared.global [%0], [%1], 16;" :: "r"(s), "l"(g));
}
__device__ __forceinline__ void red2(float* p, float a, float b) {
    asm volatile("red.global.add.v2.f32 [%0], {%1, %2};" :: "l"(p), "f"(a), "f"(b) : "memory");
}
__device__ __forceinline__ void red1(float* p, float a) {
    asm volatile("red.global.add.f32 [%0], %1;" :: "l"(p), "f"(a) : "memory");
}

#define LDMX4T(R, A) \
    asm volatile("ldmatrix.sync.aligned.m8n8.x4.trans.shared.b16 {%0,%1,%2,%3}, [%4];" \
        : "=r"((R)[0]), "=r"((R)[1]), "=r"((R)[2]), "=r"((R)[3]) : "r"(A))

#define MMA16816(C, A, B0, B1) \
    asm volatile("mma.sync.aligned.m16n8k16.row.col.f32.bf16.bf16.f32 " \
        "{%0,%1,%2,%3}, {%4,%5,%6,%7}, {%8,%9}, {%0,%1,%2,%3};" \
        : "+f"((C)[0]), "+f"((C)[1]), "+f"((C)[2]), "+f"((C)[3]) \
        : "r"((A)[0]), "r"((A)[1]), "r"((A)[2]), "r"((A)[3]), "r"(B0), "r"(B1))

// ---------------------------------------------------------------------------
// 0) init: out = -0.5 everywhere (REDs accumulate on top)
// ---------------------------------------------------------------------------
__global__ void __launch_bounds__(256)
init_kernel(float4* __restrict__ out4) {
    int i = blockIdx.x * 256 + threadIdx.x;
    out4[i] = make_float4(-0.5f, -0.5f, -0.5f, -0.5f);
}

// ---------------------------------------------------------------------------
// 1) Streaming convert: g_xb[i] = bf16(x[i]); x is dead after this -> __ldcs
// ---------------------------------------------------------------------------
__global__ void __launch_bounds__(256)
cvt_kernel(const float* __restrict__ x) {
    size_t i = ((size_t)blockIdx.x * 256 + threadIdx.x) * 16;
    float4 v[4];
#pragma unroll
    for (int j = 0; j < 4; j++) v[j] = __ldcs((const float4*)(x + i + 4 * j));
#pragma unroll
    for (int j = 0; j < 4; j += 2) {
        union { __nv_bfloat162 h2[4]; uint4 u; } p;
        p.h2[0] = __floats2bfloat162_rn(v[j].x, v[j].y);
        p.h2[1] = __floats2bfloat162_rn(v[j].z, v[j].w);
        p.h2[2] = __floats2bfloat162_rn(v[j + 1].x, v[j + 1].y);
        p.h2[3] = __floats2bfloat162_rn(v[j + 1].z, v[j + 1].w);
        *(uint4*)(g_xb + i + 4 * j) = p.u;
    }
}

// ---------------------------------------------------------------------------
// 2) bf16 SYRK: 128x128 tiles, 8 warps (2m x 4n), 64x32 per warp.
//    smem tile layout: [k][m], 64 k-rows of 128 bf16 (256B data + 16B pad).
// ---------------------------------------------------------------------------
__device__ __forceinline__ void load_chunk(uint32_t sA, int k0,
                                           int colA, int colB,
                                           bool diag, int tid) {
#pragma unroll
    for (int i = 0; i < 4; i++) {
        int idx = tid + i * 256;        // 0..1023
        int k   = idx >> 4;             // 0..63
        int ch  = idx & 15;             // 16B chunk in the 256B row
        uint32_t dst = (uint32_t)k * KSB + (uint32_t)ch * 16;
        const __nv_bfloat16* g = g_xb + (size_t)(k0 + k) * D + ch * 8;
        cp16(sA + dst, g + colA);
        if (!diag) cp16(sA + TILE_B + dst, g + colB);
    }
    asm volatile("cp.async.commit_group;" ::: "memory");
}

extern __shared__ char dyn_smem[];

__global__ void __launch_bounds__(256, 2)
gram_bf16(float* __restrict__ out, int nchunks_total, float hscale) {
    int bx = blockIdx.x;
    int tile = bx % NTILES, split = bx / NTILES;
    int I = 0, t = tile;
    while (t >= NT - I) { t -= NT - I; I++; }
    int J = I + t;
    bool diag = (I == J);
    int colA = I * BT, colB = J * BT;

    int c0 = split * nchunks_total / NSPLIT;
    int c1 = (split + 1) * nchunks_total / NSPLIT;
    int nch = c1 - c0;

    int tid = threadIdx.x, lane = tid & 31, warp = tid >> 5;
    int wm = warp & 1, wn = warp >> 1;
    int r = lane & 7, sel = lane >> 3;
    uint32_t sbase = saddr(dyn_smem);

    // ldmatrix.x4.trans per-lane offsets (within a tile buffer)
    uint32_t aoff = (uint32_t)((sel >> 1) * 8 + r) * KSB +
                    (uint32_t)(wm * 64 + (sel & 1) * 8) * 2;
    uint32_t boff = (uint32_t)((sel & 1) * 8 + r) * KSB +
                    (uint32_t)(wn * 32 + (sel >> 1) * 8) * 2;

    float c[4][4][4];
#pragma unroll
    for (int mi = 0; mi < 4; mi++)
#pragma unroll
        for (int ni = 0; ni < 4; ni++)
#pragma unroll
            for (int q = 0; q < 4; q++) c[mi][ni][q] = 0.0f;

    // prologue: 2 chunks in flight
    load_chunk(sbase,           (c0 + 0) * KCH, colA, colB, diag, tid);
    load_chunk(sbase + STAGE_B, (c0 + 1) * KCH, colA, colB, diag, tid);

    for (int ch = 0; ch < nch; ch++) {
        if (ch < nch - 1) asm volatile("cp.async.wait_group 1;" ::: "memory");
        else              asm volatile("cp.async.wait_group 0;" ::: "memory");
        __syncthreads();
        // prefetch 2 ahead into slot (ch+2)%3 (chunk ch-1 fully consumed)
        int nxt = ch + 2;
        if (nxt < nch)
            load_chunk(sbase + (nxt % NSTAGE) * STAGE_B, (c0 + nxt) * KCH,
                       colA, colB, diag, tid);

        uint32_t sA = sbase + (ch % NSTAGE) * STAGE_B;
        uint32_t sB = diag ? sA : sA + TILE_B;

#pragma unroll
        for (int step = 0; step < KCH / 16; step++) {
            uint32_t kb = (uint32_t)step * (16 * KSB);
            uint32_t a[4][4];
#pragma unroll
            for (int mi = 0; mi < 4; mi++)
                LDMX4T(a[mi], sA + kb + aoff + mi * 32);        // +16 m = +32B
            uint32_t b[2][4];
#pragma unroll
            for (int p = 0; p < 2; p++)
                LDMX4T(b[p], sB + kb + boff + p * 32);          // +16 n = +32B
#pragma unroll
            for (int mi = 0; mi < 4; mi++)
#pragma unroll
                for (int ni = 0; ni < 4; ni++) {
                    uint32_t* bp = b[ni >> 1];
                    if (ni & 1) MMA16816(c[mi][ni], a[mi], bp[2], bp[3]);
                    else        MMA16816(c[mi][ni], a[mi], bp[0], bp[1]);
                }
        }
    }

    // epilogue: scale and RED-accumulate directly into out (direct + mirror)
    int mw = I * BT + wm * 64 + (lane >> 2);
    int nw = J * BT + wn * 32 + 2 * (lane & 3);

#pragma unroll
    for (int mi = 0; mi < 4; mi++) {
        int m = mw + mi * 16;
#pragma unroll
        for (int ni = 0; ni < 4; ni++) {
            int n = nw + ni * 8;
            float v0 = hscale * c[mi][ni][0], v1 = hscale * c[mi][ni][1];
            float v2 = hscale * c[mi][ni][2], v3 = hscale * c[mi][ni][3];
            red2(&out[(size_t)m * D + n],       v0, v1);
            red2(&out[(size_t)(m + 8) * D + n], v2, v3);
            if (!diag) {
                red1(&out[(size_t)n * D + m],           v0);
                red1(&out[(size_t)(n + 1) * D + m],     v1);
                red1(&out[(size_t)n * D + m + 8],       v2);
                red1(&out[(size_t)(n + 1) * D + m + 8], v3);
            }
        }
    }
}

extern "C" void kernel_launch(void* const* d_in, const int* in_sizes, int n_in,
                              void* d_out, int out_size) {
    const float* x = (const float*)d_in[0];
    float* out = (float*)d_out;
    int N = in_sizes[0] / D;            // 16384
    int nchunks = N / KCH;              // 256

    init_kernel<<<(D * D / 4) / 256, 256>>>((float4*)out);

    int nelem = N * D;                  // 12,582,912
    cvt_kernel<<<nelem / (256 * 16), 256>>>(x);

    cudaFuncSetAttribute(gram_bf16, cudaFuncAttributeMaxDynamicSharedMemorySize,
                         DYN_SMEM);
    gram_bf16<<<NTILES * NSPLIT, 256, DYN_SMEM>>>(out, nchunks, 0.5f / (float)N);
}

// round 12
// speedup vs baseline: 1.6159x; 1.0240x over previous
#include <cuda_runtime.h>
#include <cuda_bf16.h>
#include <cstdint>
#include <cstddef>

// DecorrelationGradient: out = 0.5 * (X^T X)/N - 0.5   (KAPPA = 0.5 algebraic collapse)
// X: [16384, 768] fp32.  out: [768, 768] fp32.
//
// (1) cvt kernel: streaming fp32->bf16 convert (no transpose) + folded
//     out = -0.5 init (first 576 blocks write one float4 each),
// (2) symmetric-tiled bf16 SYRK via mma.sync.m16n8k16 + ldmatrix.trans,
//     split-K=14, epilogue RED-accumulates scaled fragments into out.
// Two launches total.

#define D        768
#define NROW     16384
#define BT       128
#define NT       6
#define NTILES   21
#define NSPLIT   14
#define KCH      64                     // k samples per pipeline chunk
#define KSB      272                    // smem row stride: 128 m * 2B + 16B pad
#define TILE_B   (KCH * KSB)            // 17408
#define STAGE_B  (2 * TILE_B)           // 34816
#define NSTAGE   3
#define DYN_SMEM (NSTAGE * STAGE_B)     // 104448
#define OUT4     (D * D / 4)            // 147456 float4 in out

__device__ __align__(16) __nv_bfloat16 g_xb[(size_t)NROW * D];   // 24 MB bf16 copy of X

__device__ __forceinline__ uint32_t saddr(const void* p) {
    return (uint32_t)__cvta_generic_to_shared(p);
}
__device__ __forceinline__ void cp16(uint32_t s, const void* g) {
    asm volatile("cp.async.cg.shared.global [%0], [%1], 16;" :: "r"(s), "l"(g));
}
__device__ __forceinline__ void red2(float* p, float a, float b) {
    asm volatile("red.global.add.v2.f32 [%0], {%1, %2};" :: "l"(p), "f"(a), "f"(b) : "memory");
}
__device__ __forceinline__ void red1(float* p, float a) {
    asm volatile("red.global.add.f32 [%0], %1;" :: "l"(p), "f"(a) : "memory");
}

#define LDMX4T(R, A) \
    asm volatile("ldmatrix.sync.aligned.m8n8.x4.trans.shared.b16 {%0,%1,%2,%3}, [%4];" \
        : "=r"((R)[0]), "=r"((R)[1]), "=r"((R)[2]), "=r"((R)[3]) : "r"(A))

#define MMA16816(C, A, B0, B1) \
    asm volatile("mma.sync.aligned.m16n8k16.row.col.f32.bf16.bf16.f32 " \
        "{%0,%1,%2,%3}, {%4,%5,%6,%7}, {%8,%9}, {%0,%1,%2,%3};" \
        : "+f"((C)[0]), "+f"((C)[1]), "+f"((C)[2]), "+f"((C)[3]) \
        : "r"((A)[0]), "r"((A)[1]), "r"((A)[2]), "r"((A)[3]), "r"(B0), "r"(B1))

// ---------------------------------------------------------------------------
// 1) Streaming convert + out init.  x is dead after this -> __ldcs.
// ---------------------------------------------------------------------------
__global__ void __launch_bounds__(256)
cvt_kernel(const float* __restrict__ x, float4* __restrict__ out4) {
    int t = blockIdx.x * 256 + threadIdx.x;
    if (t < OUT4)
        out4[t] = make_float4(-0.5f, -0.5f, -0.5f, -0.5f);

    size_t i = (size_t)t * 16;
    float4 v[4];
#pragma unroll
    for (int j = 0; j < 4; j++) v[j] = __ldcs((const float4*)(x + i + 4 * j));
#pragma unroll
    for (int j = 0; j < 4; j += 2) {
        union { __nv_bfloat162 h2[4]; uint4 u; } p;
        p.h2[0] = __floats2bfloat162_rn(v[j].x, v[j].y);
        p.h2[1] = __floats2bfloat162_rn(v[j].z, v[j].w);
        p.h2[2] = __floats2bfloat162_rn(v[j + 1].x, v[j + 1].y);
        p.h2[3] = __floats2bfloat162_rn(v[j + 1].z, v[j + 1].w);
        *(uint4*)(g_xb + i + 4 * j) = p.u;
    }
}

// ---------------------------------------------------------------------------
// 2) bf16 SYRK: 128x128 tiles, 8 warps (2m x 4n), 64x32 per warp.
//    smem tile layout: [k][m], 64 k-rows of 128 bf16 (256B data + 16B pad).
// ---------------------------------------------------------------------------
__device__ __forceinline__ void load_chunk(uint32_t sA, int k0,
                                           int colA, int colB,
                                           bool diag, int tid) {
#pragma unroll
    for (int i = 0; i < 4; i++) {
        int idx = tid + i * 256;        // 0..1023
        int k   = idx >> 4;             // 0..63
        int ch  = idx & 15;             // 16B chunk in the 256B row
        uint32_t dst = (uint32_t)k * KSB + (uint32_t)ch * 16;
        const __nv_bfloat16* g = g_xb + (size_t)(k0 + k) * D + ch * 8;
        cp16(sA + dst, g + colA);
        if (!diag) cp16(sA + TILE_B + dst, g + colB);
    }
    asm volatile("cp.async.commit_group;" ::: "memory");
}

extern __shared__ char dyn_smem[];

__global__ void __launch_bounds__(256, 2)
gram_bf16(float* __restrict__ out, int nchunks_total, float hscale) {
    int bx = blockIdx.x;
    int tile = bx % NTILES, split = bx / NTILES;
    int I = 0, t = tile;
    while (t >= NT - I) { t -= NT - I; I++; }
    int J = I + t;
    bool diag = (I == J);
    int colA = I * BT, colB = J * BT;

    int c0 = split * nchunks_total / NSPLIT;
    int c1 = (split + 1) * nchunks_total / NSPLIT;
    int nch = c1 - c0;

    int tid = threadIdx.x, lane = tid & 31, warp = tid >> 5;
    int wm = warp & 1, wn = warp >> 1;
    int r = lane & 7, sel = lane >> 3;
    uint32_t sbase = saddr(dyn_smem);

    // ldmatrix.x4.trans per-lane offsets (within a tile buffer)
    uint32_t aoff = (uint32_t)((sel >> 1) * 8 + r) * KSB +
                    (uint32_t)(wm * 64 + (sel & 1) * 8) * 2;
    uint32_t boff = (uint32_t)((sel & 1) * 8 + r) * KSB +
                    (uint32_t)(wn * 32 + (sel >> 1) * 8) * 2;

    float c[4][4][4];
#pragma unroll
    for (int mi = 0; mi < 4; mi++)
#pragma unroll
        for (int ni = 0; ni < 4; ni++)
#pragma unroll
            for (int q = 0; q < 4; q++) c[mi][ni][q] = 0.0f;

    // prologue: 2 chunks in flight
    load_chunk(sbase,           (c0 + 0) * KCH, colA, colB, diag, tid);
    load_chunk(sbase + STAGE_B, (c0 + 1) * KCH, colA, colB, diag, tid);

    for (int ch = 0; ch < nch; ch++) {
        if (ch < nch - 1) asm volatile("cp.async.wait_group 1;" ::: "memory");
        else              asm volatile("cp.async.wait_group 0;" ::: "memory");
        __syncthreads();
        // prefetch 2 ahead into slot (ch+2)%3 (chunk ch-1 fully consumed)
        int nxt = ch + 2;
        if (nxt < nch)
            load_chunk(sbase + (nxt % NSTAGE) * STAGE_B, (c0 + nxt) * KCH,
                       colA, colB, diag, tid);

        uint32_t sA = sbase + (ch % NSTAGE) * STAGE_B;
        uint32_t sB = diag ? sA : sA + TILE_B;

#pragma unroll
        for (int step = 0; step < KCH / 16; step++) {
            uint32_t kb = (uint32_t)step * (16 * KSB);
            uint32_t a[4][4];
#pragma unroll
            for (int mi = 0; mi < 4; mi++)
                LDMX4T(a[mi], sA + kb + aoff + mi * 32);        // +16 m = +32B
            uint32_t b[2][4];
#pragma unroll
            for (int p = 0; p < 2; p++)
                LDMX4T(b[p], sB + kb + boff + p * 32);          // +16 n = +32B
#pragma unroll
            for (int mi = 0; mi < 4; mi++)
#pragma unroll
                for (int ni = 0; ni < 4; ni++) {
                    uint32_t* bp = b[ni >> 1];
                    if (ni & 1) MMA16816(c[mi][ni], a[mi], bp[2], bp[3]);
                    else        MMA16816(c[mi][ni], a[mi], bp[0], bp[1]);
                }
        }
    }

    // epilogue: scale and RED-accumulate directly into out (direct + mirror)
    int mw = I * BT + wm * 64 + (lane >> 2);
    int nw = J * BT + wn * 32 + 2 * (lane & 3);

#pragma unroll
    for (int mi = 0; mi < 4; mi++) {
        int m = mw + mi * 16;
#pragma unroll
        for (int ni = 0; ni < 4; ni++) {
            int n = nw + ni * 8;
            float v0 = hscale * c[mi][ni][0], v1 = hscale * c[mi][ni][1];
            float v2 = hscale * c[mi][ni][2], v3 = hscale * c[mi][ni][3];
            red2(&out[(size_t)m * D + n],       v0, v1);
            red2(&out[(size_t)(m + 8) * D + n], v2, v3);
            if (!diag) {
                red1(&out[(size_t)n * D + m],           v0);
                red1(&out[(size_t)(n + 1) * D + m],     v1);
                red1(&out[(size_t)n * D + m + 8],       v2);
                red1(&out[(size_t)(n + 1) * D + m + 8], v3);
            }
        }
    }
}

extern "C" void kernel_launch(void* const* d_in, const int* in_sizes, int n_in,
                              void* d_out, int out_size) {
    const float* x = (const float*)d_in[0];
    float* out = (float*)d_out;
    int N = in_sizes[0] / D;            // 16384
    int nchunks = N / KCH;              // 256

    int nelem = N * D;                  // 12,582,912
    cvt_kernel<<<nelem / (256 * 16), 256>>>(x, (float4*)out);

    cudaFuncSetAttribute(gram_bf16, cudaFuncAttributeMaxDynamicSharedMemorySize,
                         DYN_SMEM);
    gram_bf16<<<NTILES * NSPLIT, 256, DYN_SMEM>>>(out, nchunks, 0.5f / (float)N);
}

// round 14
// speedup vs baseline: 1.6233x; 1.0046x over previous
#include <cuda_runtime.h>
#include <cuda_bf16.h>
#include <cstdint>
#include <cstddef>

// DecorrelationGradient: out = 0.5 * (X^T X)/N - 0.5   (KAPPA = 0.5 algebraic collapse)
// X: [16384, 768] fp32.  out: [768, 768] fp32.
//
// R14: R13 occupancy plan with the loader bug fixed (384 chunks / 192 threads
// = 2 iterations, not 4 — the stale i<4 read g_xb rows past N and trapped).
// Warp tile 48x32, CTA tile 96x96, 6 warps, launch_bounds(192,4) -> 24 warps/SM.
// 8x8 symmetric tiling, split-K=16, RED epilogue into out.

#define D        768
#define NROW     16384
#define BT       96
#define NT       8
#define NTILES   36                     // NT*(NT+1)/2
#define NSPLIT   16
#define KCH      32                     // k samples per pipeline chunk
#define KSB      208                    // smem row stride: 96 m * 2B + 16B pad
#define TILE_B   (KCH * KSB)            // 6656
#define STAGE_B  (2 * TILE_B)           // 13312
#define NSTAGE   3
#define DYN_SMEM (NSTAGE * STAGE_B)     // 39936
#define OUT4     (D * D / 4)            // 147456 float4 in out

__device__ __align__(16) __nv_bfloat16 g_xb[(size_t)NROW * D];   // 24 MB bf16 copy of X

__device__ __forceinline__ uint32_t saddr(const void* p) {
    return (uint32_t)__cvta_generic_to_shared(p);
}
__device__ __forceinline__ void cp16(uint32_t s, const void* g) {
    asm volatile("cp.async.cg.shared.global [%0], [%1], 16;" :: "r"(s), "l"(g));
}
__device__ __forceinline__ void red2(float* p, float a, float b) {
    asm volatile("red.global.add.v2.f32 [%0], {%1, %2};" :: "l"(p), "f"(a), "f"(b) : "memory");
}
__device__ __forceinline__ void red1(float* p, float a) {
    asm volatile("red.global.add.f32 [%0], %1;" :: "l"(p), "f"(a) : "memory");
}

#define LDMX4T(R, A) \
    asm volatile("ldmatrix.sync.aligned.m8n8.x4.trans.shared.b16 {%0,%1,%2,%3}, [%4];" \
        : "=r"((R)[0]), "=r"((R)[1]), "=r"((R)[2]), "=r"((R)[3]) : "r"(A))

#define MMA16816(C, A, B0, B1) \
    asm volatile("mma.sync.aligned.m16n8k16.row.col.f32.bf16.bf16.f32 " \
        "{%0,%1,%2,%3}, {%4,%5,%6,%7}, {%8,%9}, {%0,%1,%2,%3};" \
        : "+f"((C)[0]), "+f"((C)[1]), "+f"((C)[2]), "+f"((C)[3]) \
        : "r"((A)[0]), "r"((A)[1]), "r"((A)[2]), "r"((A)[3]), "r"(B0), "r"(B1))

// ---------------------------------------------------------------------------
// 1) Streaming convert + out init.  x is dead after this -> __ldcs.
// ---------------------------------------------------------------------------
__global__ void __launch_bounds__(256)
cvt_kernel(const float* __restrict__ x, float4* __restrict__ out4) {
    int t = blockIdx.x * 256 + threadIdx.x;
    if (t < OUT4)
        out4[t] = make_float4(-0.5f, -0.5f, -0.5f, -0.5f);

    size_t i = (size_t)t * 16;
    float4 v[4];
#pragma unroll
    for (int j = 0; j < 4; j++) v[j] = __ldcs((const float4*)(x + i + 4 * j));
#pragma unroll
    for (int j = 0; j < 4; j += 2) {
        union { __nv_bfloat162 h2[4]; uint4 u; } p;
        p.h2[0] = __floats2bfloat162_rn(v[j].x, v[j].y);
        p.h2[1] = __floats2bfloat162_rn(v[j].z, v[j].w);
        p.h2[2] = __floats2bfloat162_rn(v[j + 1].x, v[j + 1].y);
        p.h2[3] = __floats2bfloat162_rn(v[j + 1].z, v[j + 1].w);
        *(uint4*)(g_xb + i + 4 * j) = p.u;
    }
}

// ---------------------------------------------------------------------------
// 2) bf16 SYRK: 96x96 tiles, 6 warps (2m x 3n), 48x32 per warp.
//    smem tile layout: [k][m], 32 k-rows of 96 bf16 (192B data + 16B pad).
//    One tile = 32 rows x 12 chunks = 384 16B chunks; 192 threads -> 2 iters.
// ---------------------------------------------------------------------------
__device__ __forceinline__ void load_chunk(uint32_t sA, int k0,
                                           int colA, int colB,
                                           bool diag, int tid) {
#pragma unroll
    for (int i = 0; i < 2; i++) {
        int idx = tid + i * 192;        // 0..383
        int k   = idx / 12;             // 0..31
        int ch  = idx % 12;             // 16B chunk in the 192B row
        uint32_t dst = (uint32_t)k * KSB + (uint32_t)ch * 16;
        const __nv_bfloat16* g = g_xb + (size_t)(k0 + k) * D + ch * 8;
        cp16(sA + dst, g + colA);
        if (!diag) cp16(sA + TILE_B + dst, g + colB);
    }
    asm volatile("cp.async.commit_group;" ::: "memory");
}

extern __shared__ char dyn_smem[];

__global__ void __launch_bounds__(192, 4)
gram_bf16(float* __restrict__ out, int nchunks_total, float hscale) {
    int bx = blockIdx.x;
    int tile = bx % NTILES, split = bx / NTILES;
    int I = 0, t = tile;
    while (t >= NT - I) { t -= NT - I; I++; }
    int J = I + t;
    bool diag = (I == J);
    int colA = I * BT, colB = J * BT;

    int c0 = split * nchunks_total / NSPLIT;
    int c1 = (split + 1) * nchunks_total / NSPLIT;
    int nch = c1 - c0;

    int tid = threadIdx.x, lane = tid & 31, warp = tid >> 5;
    int wm = warp & 1, wn = warp >> 1;       // 2m x 3n
    int r = lane & 7, sel = lane >> 3;
    uint32_t sbase = saddr(dyn_smem);

    // ldmatrix.x4.trans per-lane offsets (within a tile buffer)
    uint32_t aoff = (uint32_t)((sel >> 1) * 8 + r) * KSB +
                    (uint32_t)(wm * 48 + (sel & 1) * 8) * 2;
    uint32_t boff = (uint32_t)((sel & 1) * 8 + r) * KSB +
                    (uint32_t)(wn * 32 + (sel >> 1) * 8) * 2;

    float c[3][4][4];
#pragma unroll
    for (int mi = 0; mi < 3; mi++)
#pragma unroll
        for (int ni = 0; ni < 4; ni++)
#pragma unroll
            for (int q = 0; q < 4; q++) c[mi][ni][q] = 0.0f;

    // prologue: 2 chunks in flight
    load_chunk(sbase,           (c0 + 0) * KCH, colA, colB, diag, tid);
    load_chunk(sbase + STAGE_B, (c0 + 1) * KCH, colA, colB, diag, tid);

    for (int ch = 0; ch < nch; ch++) {
        if (ch < nch - 1) asm volatile("cp.async.wait_group 1;" ::: "memory");
        else              asm volatile("cp.async.wait_group 0;" ::: "memory");
        __syncthreads();
        // prefetch 2 ahead into slot (ch+2)%3 (chunk ch-1 fully consumed)
        int nxt = ch + 2;
        if (nxt < nch)
            load_chunk(sbase + (nxt % NSTAGE) * STAGE_B, (c0 + nxt) * KCH,
                       colA, colB, diag, tid);

        uint32_t sA = sbase + (ch % NSTAGE) * STAGE_B;
        uint32_t sB = diag ? sA : sA + TILE_B;

#pragma unroll
        for (int step = 0; step < KCH / 16; step++) {
            uint32_t kb = (uint32_t)step * (16 * KSB);
            uint32_t a[3][4];
#pragma unroll
            for (int mi = 0; mi < 3; mi++)
                LDMX4T(a[mi], sA + kb + aoff + mi * 32);        // +16 m = +32B
            uint32_t b[2][4];
#pragma unroll
            for (int p = 0; p < 2; p++)
                LDMX4T(b[p], sB + kb + boff + p * 32);          // +16 n = +32B
#pragma unroll
            for (int mi = 0; mi < 3; mi++)
#pragma unroll
                for (int ni = 0; ni < 4; ni++) {
                    uint32_t* bp = b[ni >> 1];
                    if (ni & 1) MMA16816(c[mi][ni], a[mi], bp[2], bp[3]);
                    else        MMA16816(c[mi][ni], a[mi], bp[0], bp[1]);
                }
        }
    }

    // epilogue: scale and RED-accumulate directly into out (direct + mirror)
    int mw = I * BT + wm * 48 + (lane >> 2);
    int nw = J * BT + wn * 32 + 2 * (lane & 3);

#pragma unroll
    for (int mi = 0; mi < 3; mi++) {
        int m = mw + mi * 16;
#pragma unroll
        for (int ni = 0; ni < 4; ni++) {
            int n = nw + ni * 8;
            float v0 = hscale * c[mi][ni][0], v1 = hscale * c[mi][ni][1];
            float v2 = hscale * c[mi][ni][2], v3 = hscale * c[mi][ni][3];
            red2(&out[(size_t)m * D + n],       v0, v1);
            red2(&out[(size_t)(m + 8) * D + n], v2, v3);
            if (!diag) {
                red1(&out[(size_t)n * D + m],           v0);
                red1(&out[(size_t)(n + 1) * D + m],     v1);
                red1(&out[(size_t)n * D + m + 8],       v2);
                red1(&out[(size_t)(n + 1) * D + m + 8], v3);
            }
        }
    }
}

extern "C" void kernel_launch(void* const* d_in, const int* in_sizes, int n_in,
                              void* d_out, int out_size) {
    const float* x = (const float*)d_in[0];
    float* out = (float*)d_out;
    int N = in_sizes[0] / D;            // 16384
    int nchunks = N / KCH;              // 512

    int nelem = N * D;                  // 12,582,912
    cvt_kernel<<<nelem / (256 * 16), 256>>>(x, (float4*)out);

    cudaFuncSetAttribute(gram_bf16, cudaFuncAttributeMaxDynamicSharedMemorySize,
                         DYN_SMEM);
    gram_bf16<<<NTILES * NSPLIT, 192, DYN_SMEM>>>(out, nchunks, 0.5f / (float)N);
}